// round 12
// baseline (speedup 1.0000x reference)
#include <cuda_runtime.h>

#define ADAM_B1 0.9f
#define ADAM_B2 0.999f
#define ADAM_LR 0.02f

// ---------------- packed f32x2 helpers ----------------
struct F2 { unsigned long long v; };

__device__ __forceinline__ F2 pk(float lo, float hi) {
    F2 r; asm("mov.b64 %0, {%1, %2};" : "=l"(r.v) : "f"(lo), "f"(hi)); return r;
}
__device__ __forceinline__ void upk(F2 a, float& lo, float& hi) {
    asm("mov.b64 {%0, %1}, %2;" : "=f"(lo), "=f"(hi) : "l"(a.v));
}
__device__ __forceinline__ F2 bc(float s) { return pk(s, s); }
__device__ __forceinline__ F2 fadd2(F2 a, F2 b) {
    F2 r; asm("add.rn.f32x2 %0, %1, %2;" : "=l"(r.v) : "l"(a.v), "l"(b.v)); return r;
}
__device__ __forceinline__ F2 fmul2(F2 a, F2 b) {
    F2 r; asm("mul.rn.f32x2 %0, %1, %2;" : "=l"(r.v) : "l"(a.v), "l"(b.v)); return r;
}
__device__ __forceinline__ F2 ffma2(F2 a, F2 b, F2 c) {
    F2 r; asm("fma.rn.f32x2 %0, %1, %2, %3;" : "=l"(r.v) : "l"(a.v), "l"(b.v), "l"(c.v)); return r;
}

__device__ __forceinline__ float rcp_a(float x) {
    float r; asm("rcp.approx.f32 %0, %1;" : "=f"(r) : "f"(x)); return r;
}
__device__ __forceinline__ float rsq_a(float x) {
    float r; asm("rsqrt.approx.f32 %0, %1;" : "=f"(r) : "f"(x)); return r;
}
__device__ __forceinline__ float sqrt_a(float x) {
    float r; asm("sqrt.approx.f32 %0, %1;" : "=f"(r) : "f"(x)); return r;
}
__device__ __forceinline__ float ex2_a(float x) {
    float r; asm("ex2.approx.f32 %0, %1;" : "=f"(r) : "f"(x)); return r;
}
__device__ __forceinline__ F2 frcp2(F2 a) {
    float lo, hi; upk(a, lo, hi); return pk(rcp_a(lo), rcp_a(hi));
}
__device__ __forceinline__ F2 frsq2(F2 a) {
    float lo, hi; upk(a, lo, hi); return pk(rsq_a(lo), rsq_a(hi));
}
#define EXPA(x) ex2_a(1.4426950408889634f * (x))

// ---------------- main kernel: 1 pixel/thread, lambda-packed, epilogue consts in smem ----------------
__global__ __launch_bounds__(32, 22)
void pe_kernel(const float* __restrict__ X,     // (B,5,5)
               const float* __restrict__ Yg,    // (B,5)
               const float* __restrict__ ch0g,  // (B,1,3)
               const float* __restrict__ pf,    // (14,)
               const float* __restrict__ xag,   // (3,)
               const float* __restrict__ Sag,   // (3,3)
               const float* __restrict__ Seg,   // (5,5)
               const int*   __restrict__ nitp,
               float* __restrict__ out,         // (B,9)
               int B)
{
    __shared__ float epi[16];   // [0..4]=KA, [5..9]=KC, [10]=KN, [11]=K0, [12..14]=C1, [15]=C2

    int b = blockIdx.x * blockDim.x + threadIdx.x;

    const float L[5] = {-0.275f, 0.025f, 0.5f, 0.70f, 1.15f};

    // ---- uniform parameter prep (also fills smem epilogue constants) ----
    float p0=pf[0], p1=pf[1], p2=pf[2], p3=pf[3], p4=pf[4], p5=pf[5], p6=pf[6],
          p7=pf[7], p8=pf[8];
    const float cna = pf[12] * 0.005f;
    const float cnb = pf[13] * 0.005f;
    const float c7s = p7 * 0.089f;
    const float c8s = p8 * 0.1245f;
    const float cnab = cna + cnb;

    float AphS[5], AcdS[5], BbsS[5];
    #pragma unroll
    for (int l = 0; l < 5; l++) {
        AphS[l] = p0 * 0.05f * (1.0f + p1 * 0.1f * L[l] + p2 * 0.01f);
        AcdS[l] = p5 * 0.1f * EXPA(-p6 * 1.7f * L[l]);
        BbsS[l] = p3 * 0.001f * (1.0f + p4 * 0.05f * L[l]);
    }

    if (threadIdx.x == 0) {
        float kfac = pf[9] * 0.9f + pf[10] * 0.1f;
        float p11v = pf[11];
        #pragma unroll
        for (int l = 0; l < 5; l++) {
            epi[l]     = kfac * (AphS[l] + BbsS[l]);
            epi[5 + l] = kfac * AcdS[l];
        }
        epi[10] = kfac * cnab;
        epi[11] = kfac * 0.0057f;
        epi[12] = p11v * BbsS[1];
        epi[13] = p11v * BbsS[2];
        epi[14] = p11v * BbsS[4];
        epi[15] = p11v * cnb;
    }
    __syncwarp();

    if (b >= B) return;

    // diagonality check on symmetrized matrices
    bool diag = ((Seg[0*5+1]+Seg[1*5+0])==0.f && (Seg[0*5+2]+Seg[2*5+0])==0.f &&
                 (Seg[0*5+3]+Seg[3*5+0])==0.f && (Seg[0*5+4]+Seg[4*5+0])==0.f &&
                 (Seg[1*5+2]+Seg[2*5+1])==0.f && (Seg[1*5+3]+Seg[3*5+1])==0.f &&
                 (Seg[1*5+4]+Seg[4*5+1])==0.f && (Seg[2*5+3]+Seg[3*5+2])==0.f &&
                 (Seg[2*5+4]+Seg[4*5+2])==0.f && (Seg[3*5+4]+Seg[4*5+3])==0.f &&
                 (Sag[0*3+1]+Sag[1*3+0])==0.f && (Sag[0*3+2]+Sag[2*3+0])==0.f &&
                 (Sag[1*3+2]+Sag[2*3+1])==0.f);

    // ---- per-pixel setup ----
    float fe[5], yv[5];
    #pragma unroll
    for (int l = 0; l < 5; l++) {
        float e0 = X[b*25 + l*5 + 0], e1 = X[b*25 + l*5 + 1];
        fe[l] = __fdividef(e0 + 0.5f*e1, e0 + e1);
        yv[l] = Yg[b*5 + l];
    }

    float ch0v = ch0g[b*3 + 0];
    float ch1v = ch0g[b*3 + 1];
    float ch2v = ch0g[b*3 + 2];

    int iters = 50;
    if (nitp) {
        int it = *nitp;
        if (it >= 1 && it <= 100000000) iters = it;
        else {
            float f = __int_as_float(it);
            if (f >= 1.0f && f <= 1e8f) iters = (int)f;
        }
    }

    float b1t = 1.0f, b2t = 1.0f;

    if (diag) {
        // ===== 1px diag path: lambda (0,1),(2,3) packed; lambda4 scalar =====
        F2 AB[2], ACD[2], BBS[2], FE2[2], YFN[2];
        #pragma unroll
        for (int i = 0; i < 2; i++) {
            int l0 = 2*i, l1 = 2*i + 1;
            AB[i]  = pk(AphS[l0] + BbsS[l0], AphS[l1] + BbsS[l1]);
            ACD[i] = pk(AcdS[l0], AcdS[l1]);
            BBS[i] = pk(BbsS[l0], BbsS[l1]);
            FE2[i] = pk(Seg[l0*5+l0]*fe[l0]*fe[l0], Seg[l1*5+l1]*fe[l1]*fe[l1]);
            YFN[i] = pk(-__fdividef(yv[l0], fe[l0]), -__fdividef(yv[l1], fe[l1]));
        }
        const float ab4 = AphS[4] + BbsS[4];
        const float acd4 = AcdS[4], bbs4 = BbsS[4];
        const float fe24 = Seg[24]*fe[4]*fe[4];
        const float yfn4 = -__fdividef(yv[4], fe[4]);

        const float sa2 = Sag[8], bp2 = -Sag[8]*xag[2];
        const F2 SA01 = pk(Sag[0], Sag[4]);
        const F2 BP01 = pk(-Sag[0]*xag[0], -Sag[4]*xag[1]);
        const F2 C7p = bc(c7s), C8p = bc(c8s), NEG1p = bc(-1.0f);
        const F2 CB1p = bc(ADAM_B1), C1MB1p = bc(1.0f - ADAM_B1);
        const F2 CB2p = bc(ADAM_B2), C1MB2p = bc(1.0f - ADAM_B2);

        F2 ch01 = pk(ch0v, ch1v);
        F2 m01 = bc(0.0f), v01 = bc(1e-30f);
        float m2 = 0.0f, v2 = 1e-30f;

        for (int t = 0; t < iters; t++) {
            b1t *= ADAM_B1; b2t *= ADAM_B2;
            float nlrt = -ADAM_LR * sqrt_a(1.0f - b2t) * rcp_a(1.0f - b1t);

            float c0, c1;
            upk(ch01, c0, c1);
            float chla = EXPA(c0);
            float nap  = EXPA(c1);
            float cdom = EXPA(ch2v);

            float NCs   = fmaf(cnab, nap, 0.0057f);
            float DB1Cs = fmaf(cnb,  nap, 0.0012f);

            F2 CHLA2 = bc(chla), CDOM2 = bc(cdom);
            F2 NC2 = bc(NCs), DB1C2 = bc(DB1Cs);

            F2 acc0p = bc(0.0f), S0p = bc(0.0f), S1p = bc(0.0f), acc2p = bc(0.0f);

            #pragma unroll
            for (int i = 0; i < 2; i++) {
                F2 s  = ffma2(AB[i], CHLA2, ffma2(ACD[i], CDOM2, NC2));
                F2 bb = ffma2(BBS[i], CHLA2, DB1C2);
                F2 iv = frcp2(s);
                F2 u  = fmul2(bb, iv);
                F2 t1 = ffma2(C8p, u, C7p);
                F2 p  = ffma2(t1, u, YFN[i]);
                F2 d  = ffma2(C8p, u, t1);
                F2 q  = fmul2(fmul2(FE2[i], iv), fmul2(p, d));
                F2 qu = fmul2(q, u);
                F2 un = fmul2(u, NEG1p);
                F2 tg = ffma2(un, AB[i], BBS[i]);
                acc0p = ffma2(q, tg, acc0p);
                S0p   = fadd2(S0p, q);
                S1p   = fadd2(S1p, qu);
                acc2p = ffma2(qu, ACD[i], acc2p);
            }

            // scalar lambda 4
            float s4  = fmaf(ab4, chla, fmaf(acd4, cdom, NCs));
            float bb4 = fmaf(bbs4, chla, DB1Cs);
            float iv4 = rcp_a(s4);
            float u4  = bb4 * iv4;
            float t14 = fmaf(c8s, u4, c7s);
            float p4v = fmaf(t14, u4, yfn4);
            float d4  = fmaf(c8s, u4, t14);
            float q4  = (fe24 * iv4) * (p4v * d4);
            float qu4 = q4 * u4;
            float tg4 = fmaf(-u4, ab4, bbs4);

            // lane reductions
            float a0l, a0h, s0l, s0h, s1l, s1h, a2l, a2h;
            upk(acc0p, a0l, a0h); upk(S0p, s0l, s0h);
            upk(S1p, s1l, s1h);   upk(acc2p, a2l, a2h);
            float acc0 = fmaf(q4, tg4, a0l + a0h);
            float S0   = (s0l + s0h) + q4;
            float S1   = (s1l + s1h) + qu4;
            float acc2 = fmaf(qu4, acd4, a2l + a2h);

            // gradients
            float gd0 = acc0 * chla;
            float tt  = fmaf(cnb, S0, -(cnab * S1));
            float gd1 = tt * nap;
            F2 g01 = fadd2(pk(gd0, gd1), ffma2(SA01, ch01, BP01));
            float g2 = fmaf(sa2, ch2v, bp2) - acc2 * cdom;

            // Adam packed (0,1)
            m01 = ffma2(g01, C1MB1p, fmul2(m01, CB1p));
            v01 = ffma2(fmul2(g01, g01), C1MB2p, fmul2(v01, CB2p));
            ch01 = ffma2(fmul2(m01, frsq2(v01)), bc(nlrt), ch01);

            // Adam scalar (2)
            m2 = fmaf(g2, 1.0f - ADAM_B1, m2 * ADAM_B1);
            v2 = fmaf(g2 * g2, 1.0f - ADAM_B2, v2 * ADAM_B2);
            ch2v = fmaf(nlrt * m2, rsq_a(v2), ch2v);
        }
        upk(ch01, ch0v, ch1v);
    } else {
        // ===== general scalar two-pass fallback (dense Se, Sa) =====
        float Se[5][5];
        #pragma unroll
        for (int i = 0; i < 5; i++)
            #pragma unroll
            for (int j = 0; j < 5; j++)
                Se[i][j] = 0.5f * (Seg[i*5 + j] + Seg[j*5 + i]);
        float SaS[3][3];
        #pragma unroll
        for (int i = 0; i < 3; i++)
            #pragma unroll
            for (int j = 0; j < 3; j++)
                SaS[i][j] = 0.5f * (Sag[i*3 + j] + Sag[j*3 + i]);
        float xa0 = xag[0], xa1 = xag[1], xa2 = xag[2];

        float ch[3] = { ch0v, ch1v, ch2v };
        float m[3] = {0.f,0.f,0.f}, v[3] = {1e-30f,1e-30f,1e-30f};
        float bp0 = -(SaS[0][0]*xa0 + SaS[0][1]*xa1 + SaS[0][2]*xa2);
        float bp1 = -(SaS[1][0]*xa0 + SaS[1][1]*xa1 + SaS[1][2]*xa2);
        float bp2 = -(SaS[2][0]*xa0 + SaS[2][1]*xa1 + SaS[2][2]*xa2);

        for (int t = 0; t < iters; t++) {
            float chla = EXPA(ch[0]);
            float nap  = EXPA(ch[1]);
            float cdom = EXPA(ch[2]);

            float da1  = cna * nap;
            float dbb1 = cnb * nap;

            float r[5], u[5], iv[5];
            #pragma unroll
            for (int l = 0; l < 5; l++) {
                float a  = 0.0045f + AphS[l]*chla + AcdS[l]*cdom + da1;
                float bb = 0.0012f + BbsS[l]*chla + dbb1;
                iv[l] = rcp_a(a + bb);
                u[l]  = bb * iv[l];
                float rrs = fmaf(c8s, u[l], c7s) * u[l] * fe[l];
                r[l] = rrs - yv[l];
            }

            float g0 = fmaf(SaS[0][0], ch[0], fmaf(SaS[0][1], ch[1], fmaf(SaS[0][2], ch[2], bp0)));
            float g1 = fmaf(SaS[1][0], ch[0], fmaf(SaS[1][1], ch[1], fmaf(SaS[1][2], ch[2], bp1)));
            float g2 = fmaf(SaS[2][0], ch[0], fmaf(SaS[2][1], ch[1], fmaf(SaS[2][2], ch[2], bp2)));

            #pragma unroll
            for (int l = 0; l < 5; l++) {
                float w = fmaf(Se[l][0], r[0], fmaf(Se[l][1], r[1],
                          fmaf(Se[l][2], r[2], fmaf(Se[l][3], r[3], Se[l][4]*r[4]))));
                float dg = fmaf(2.0f*c8s, u[l], c7s) * fe[l];
                float q  = w * dg * iv[l];
                float ul = u[l], om = 1.0f - ul;
                float da0 = AphS[l]*chla, dbb0 = BbsS[l]*chla;
                float da2 = AcdS[l]*cdom;
                g0 += q * (om * dbb0 - ul * da0);
                g1 += q * (om * dbb1 - ul * da1);
                g2 -= q * ul * da2;
            }

            b1t *= ADAM_B1; b2t *= ADAM_B2;
            float nlrt = -ADAM_LR * sqrt_a(1.0f - b2t) * rcp_a(1.0f - b1t);
            float g[3] = { g0, g1, g2 };
            #pragma unroll
            for (int k = 0; k < 3; k++) {
                m[k] = fmaf(g[k], 1.0f - ADAM_B1, m[k] * ADAM_B1);
                v[k] = fmaf(g[k] * g[k], 1.0f - ADAM_B2, v[k] * ADAM_B2);
                ch[k] += nlrt * m[k] * rsq_a(v[k]);
            }
        }
        ch0v = ch[0]; ch1v = ch[1]; ch2v = ch[2];
    }

    // ---- outputs: [ch0, kd(5), bbp(3)] — constants from smem ----
    {
        float chla = EXPA(ch0v);
        float nap  = EXPA(ch1v);
        float cdom = EXPA(ch2v);
        float KN = epi[10], K0 = epi[11];
        float knn = fmaf(KN, nap, K0);
        float c2n = epi[15] * nap;

        out[b*9 + 0] = ch0v;
        #pragma unroll
        for (int l = 0; l < 5; l++) {
            float kab = fmaf(epi[l], chla, fmaf(epi[5 + l], cdom, knn));
            float x3 = X[b*25 + l*5 + 3];
            float mu = 0.5f + 0.5f * rcp_a(1.0f + EXPA(-x3));
            out[b*9 + 1 + l] = kab * rcp_a(mu);
        }
        #pragma unroll
        for (int j = 0; j < 3; j++) {
            out[b*9 + 6 + j] = fmaf(epi[12 + j], chla, c2n);
        }
    }
}

extern "C" void kernel_launch(void* const* d_in, const int* in_sizes, int n_in,
                              void* d_out, int out_size) {
    const float* X    = (const float*)d_in[0];
    const float* Y    = (const float*)d_in[1];
    const float* ch0  = (const float*)d_in[2];
    const float* pf   = (const float*)d_in[3];
    const float* xa   = (const float*)d_in[4];
    const float* Sa   = (const float*)d_in[5];
    const float* Se   = (const float*)d_in[6];
    const int*   nit  = (n_in >= 8) ? (const int*)d_in[7] : nullptr;
    float* out = (float*)d_out;

    int B = in_sizes[1] / 5;   // Y is (B,5)

    const int TPB = 32;
    int blocks = (B + TPB - 1) / TPB;
    pe_kernel<<<blocks, TPB>>>(X, Y, ch0, pf, xa, Sa, Se, nit, out, B);
}

// round 13
// speedup vs baseline: 1.0992x; 1.0992x over previous
#include <cuda_runtime.h>

#define ADAM_B1 0.9f
#define ADAM_B2 0.999f
#define ADAM_LR 0.02f
#define LOG2E_F 1.4426950408889634f
#define LN2_F   0.6931471805599453f

// ---------------- packed f32x2 helpers ----------------
struct F2 { unsigned long long v; };

__device__ __forceinline__ F2 pk(float lo, float hi) {
    F2 r; asm("mov.b64 %0, {%1, %2};" : "=l"(r.v) : "f"(lo), "f"(hi)); return r;
}
__device__ __forceinline__ void upk(F2 a, float& lo, float& hi) {
    asm("mov.b64 {%0, %1}, %2;" : "=f"(lo), "=f"(hi) : "l"(a.v));
}
__device__ __forceinline__ F2 bc(float s) { return pk(s, s); }
__device__ __forceinline__ F2 fadd2(F2 a, F2 b) {
    F2 r; asm("add.rn.f32x2 %0, %1, %2;" : "=l"(r.v) : "l"(a.v), "l"(b.v)); return r;
}
__device__ __forceinline__ F2 fmul2(F2 a, F2 b) {
    F2 r; asm("mul.rn.f32x2 %0, %1, %2;" : "=l"(r.v) : "l"(a.v), "l"(b.v)); return r;
}
__device__ __forceinline__ F2 ffma2(F2 a, F2 b, F2 c) {
    F2 r; asm("fma.rn.f32x2 %0, %1, %2, %3;" : "=l"(r.v) : "l"(a.v), "l"(b.v), "l"(c.v)); return r;
}

__device__ __forceinline__ float rcp_a(float x) {
    float r; asm("rcp.approx.f32 %0, %1;" : "=f"(r) : "f"(x)); return r;
}
__device__ __forceinline__ float rsq_a(float x) {
    float r; asm("rsqrt.approx.f32 %0, %1;" : "=f"(r) : "f"(x)); return r;
}
__device__ __forceinline__ float sqrt_a(float x) {
    float r; asm("sqrt.approx.f32 %0, %1;" : "=f"(r) : "f"(x)); return r;
}
__device__ __forceinline__ float ex2_a(float x) {
    float r; asm("ex2.approx.f32 %0, %1;" : "=f"(r) : "f"(x)); return r;
}
__device__ __forceinline__ F2 frcp2(F2 a) {
    float lo, hi; upk(a, lo, hi); return pk(rcp_a(lo), rcp_a(hi));
}
__device__ __forceinline__ F2 frsq2(F2 a) {
    float lo, hi; upk(a, lo, hi); return pk(rsq_a(lo), rsq_a(hi));
}
// 2^x per lane (no pre-multiply — operand already in log2 domain)
__device__ __forceinline__ F2 fex2raw(F2 a) {
    float lo, hi; upk(a, lo, hi);
    return pk(ex2_a(lo), ex2_a(hi));
}
__device__ __forceinline__ F2 fexp2(F2 a) {   // e^x (packed), for dense fallback
    F2 t = fmul2(a, bc(LOG2E_F));
    return fex2raw(t);
}
#define EXPA(x) ex2_a(LOG2E_F * (x))

// ---------------- main kernel: 2 pixels per thread, log2-domain state ----------------
__global__ __launch_bounds__(32)
void pe_kernel(const float* __restrict__ X,     // (B,5,5)
               const float* __restrict__ Yg,    // (B,5)
               const float* __restrict__ ch0g,  // (B,1,3)
               const float* __restrict__ pf,    // (14,)
               const float* __restrict__ xag,   // (3,)
               const float* __restrict__ Sag,   // (3,3)
               const float* __restrict__ Seg,   // (5,5)
               const int*   __restrict__ nitp,
               float* __restrict__ out,         // (B,9)
               int B)
{
    int tIdx = blockIdx.x * blockDim.x + threadIdx.x;
    int pA = 2 * tIdx;
    if (pA >= B) return;
    int pB = min(pA + 1, B - 1);

    const float L[5] = {-0.275f, 0.025f, 0.5f, 0.70f, 1.15f};

    // ---- uniform (broadcast) parameters ----
    float p0=pf[0], p1=pf[1], p2=pf[2], p3=pf[3], p4=pf[4], p5=pf[5], p6=pf[6],
          p7=pf[7], p8=pf[8], p9=pf[9], p10=pf[10], p11=pf[11], p12=pf[12], p13=pf[13];

    float AphS[5], AcdS[5], BbsS[5];
    #pragma unroll
    for (int l = 0; l < 5; l++) {
        AphS[l] = p0 * 0.05f * (1.0f + p1 * 0.1f * L[l] + p2 * 0.01f);
        AcdS[l] = p5 * 0.1f * expf(-p6 * 1.7f * L[l]);
        BbsS[l] = p3 * 0.001f * (1.0f + p4 * 0.05f * L[l]);
    }
    const float cna = p12 * 0.005f;
    const float cnb = p13 * 0.005f;
    const float c7s = p7 * 0.089f;
    const float c8s = p8 * 0.1245f;

    // symmetrized matrices (uniform)
    float Se[5][5];
    #pragma unroll
    for (int i = 0; i < 5; i++)
        #pragma unroll
        for (int j = 0; j < 5; j++)
            Se[i][j] = 0.5f * (Seg[i*5 + j] + Seg[j*5 + i]);
    float SaS[3][3];
    #pragma unroll
    for (int i = 0; i < 3; i++)
        #pragma unroll
        for (int j = 0; j < 3; j++)
            SaS[i][j] = 0.5f * (Sag[i*3 + j] + Sag[j*3 + i]);
    float xa0 = xag[0], xa1 = xag[1], xa2 = xag[2];

    bool diag = (Se[0][1]==0.f && Se[0][2]==0.f && Se[0][3]==0.f && Se[0][4]==0.f &&
                 Se[1][2]==0.f && Se[1][3]==0.f && Se[1][4]==0.f &&
                 Se[2][3]==0.f && Se[2][4]==0.f && Se[3][4]==0.f &&
                 SaS[0][1]==0.f && SaS[0][2]==0.f && SaS[1][2]==0.f);

    // ---- per-pixel setup ----
    float feA[5], feB[5];
    #pragma unroll
    for (int l = 0; l < 5; l++) {
        float eA0 = X[pA*25 + l*5 + 0], eA1 = X[pA*25 + l*5 + 1];
        float eB0 = X[pB*25 + l*5 + 0], eB1 = X[pB*25 + l*5 + 1];
        feA[l] = __fdividef(eA0 + 0.5f*eA1, eA0 + eA1);
        feB[l] = __fdividef(eB0 + 0.5f*eB1, eB0 + eB1);
    }

    F2 m[3], v[3];
    #pragma unroll
    for (int k = 0; k < 3; k++) { m[k] = bc(0.0f); v[k] = bc(1e-30f); }

    int iters = 50;
    if (nitp) {
        int it = *nitp;
        if (it >= 1 && it <= 100000000) iters = it;
        else {
            float f = __int_as_float(it);
            if (f >= 1.0f && f <= 1e8f) iters = (int)f;
        }
    }

    float b1t = 1.0f, b2t = 1.0f;
    float chOutA[3], chOutB[3];   // final ch values (natural-log domain)

    if (diag) {
        // ===== lean fused diagonal path — state cl = ch*log2(e) =====
        F2 cl[3];
        #pragma unroll
        for (int k = 0; k < 3; k++)
            cl[k] = pk(ch0g[pA*3 + k] * LOG2E_F, ch0g[pB*3 + k] * LOG2E_F);

        F2 ABSp[5], ACDp[5], BBSp[5], FE2[5], YFN[5];
        #pragma unroll
        for (int l = 0; l < 5; l++) {
            ABSp[l] = bc(AphS[l] + BbsS[l]);
            ACDp[l] = bc(AcdS[l]);
            BBSp[l] = bc(BbsS[l]);
            FE2[l]  = pk(Se[l][l]*feA[l]*feA[l], Se[l][l]*feB[l]*feB[l]);
            YFN[l]  = pk(-__fdividef(Yg[pA*5 + l], feA[l]),
                         -__fdividef(Yg[pB*5 + l], feB[l]));
        }
        // prior: Sa*(ch - xa) = (Sa*ln2)*cl - Sa*xa
        const F2 SADl2[3] = { bc(SaS[0][0]*LN2_F), bc(SaS[1][1]*LN2_F), bc(SaS[2][2]*LN2_F) };
        const F2 BPD[3]   = { bc(-SaS[0][0]*xa0),  bc(-SaS[1][1]*xa1),  bc(-SaS[2][2]*xa2) };
        const F2 CNAB  = bc(cna + cnb);
        const F2 CNBp  = bc(cnb);
        const F2 CNABn = bc(-(cna + cnb));
        const F2 C7p = bc(c7s), C8p = bc(c8s);
        const F2 C0057 = bc(0.0057f), C0012 = bc(0.0012f);
        const F2 NEG1 = bc(-1.0f);
        const F2 CB1p = bc(ADAM_B1), C1MB1p = bc(1.0f - ADAM_B1);
        const F2 CB2p = bc(ADAM_B2), C1MB2p = bc(1.0f - ADAM_B2);

        for (int t = 0; t < iters; t++) {
            // scalar step size; fold log2(e) domain conversion in
            b1t *= ADAM_B1; b2t *= ADAM_B2;
            float nlrt = (-ADAM_LR * LOG2E_F) * sqrt_a(1.0f - b2t) * rcp_a(1.0f - b1t);
            F2 NLRT2 = bc(nlrt);

            // direct 2^cl (MUFU; no pre-multiply)
            F2 chla = fex2raw(cl[0]);
            F2 nap  = fex2raw(cl[1]);
            F2 cdom = fex2raw(cl[2]);

            F2 NC   = ffma2(CNAB, nap, C0057);
            F2 DB1C = ffma2(CNBp, nap, C0012);

            F2 a0e = bc(0.0f), a0o = bc(0.0f);
            F2 Te  = bc(0.0f), To  = bc(0.0f);
            F2 a2e = bc(0.0f), a2o = bc(0.0f);

            #pragma unroll
            for (int l = 0; l < 5; l++) {
                F2 s  = ffma2(ABSp[l], chla, ffma2(ACDp[l], cdom, NC)); // a+bb
                F2 bb = ffma2(BBSp[l], chla, DB1C);
                F2 iv = frcp2(s);
                F2 u  = fmul2(bb, iv);
                F2 t1 = ffma2(C8p, u, C7p);
                F2 p  = ffma2(t1, u, YFN[l]);        // rrs/FE - Y/FE
                F2 d  = ffma2(C8p, u, t1);           // c7 + 2 c8 u
                F2 q  = fmul2(fmul2(FE2[l], iv), fmul2(p, d));
                F2 qu = fmul2(q, u);
                F2 un = fmul2(u, NEG1);
                F2 tg = ffma2(un, ABSp[l], BBSp[l]); // BBS - u*(Aph+Bbs)
                if (l & 1) {
                    a0o = ffma2(q, tg, a0o);
                    To  = ffma2(CNBp, q, To);
                    To  = ffma2(CNABn, qu, To);
                    a2o = ffma2(qu, ACDp[l], a2o);
                } else {
                    a0e = ffma2(q, tg, a0e);
                    Te  = ffma2(CNBp, q, Te);
                    Te  = ffma2(CNABn, qu, Te);
                    a2e = ffma2(qu, ACDp[l], a2e);
                }
            }
            F2 acc0 = fadd2(a0e, a0o);
            F2 T    = fadd2(Te, To);
            F2 acc2n = fadd2(a2e, a2o);   // = +sum qu*ACD  (gradient is minus this * cdom)

            // gradients (wrt ch; prior via log2-domain fold)
            F2 g0 = ffma2(acc0, chla, ffma2(SADl2[0], cl[0], BPD[0]));
            F2 g1 = ffma2(T,    nap,  ffma2(SADl2[1], cl[1], BPD[1]));
            F2 g2m = fmul2(acc2n, cdom);
            F2 g2 = ffma2(g2m, NEG1, ffma2(SADl2[2], cl[2], BPD[2]));

            F2 g[3] = { g0, g1, g2 };
            #pragma unroll
            for (int k = 0; k < 3; k++) {
                m[k] = ffma2(g[k], C1MB1p, fmul2(m[k], CB1p));
                v[k] = ffma2(fmul2(g[k], g[k]), C1MB2p, fmul2(v[k], CB2p));
                F2 st = frsq2(v[k]);
                cl[k] = ffma2(fmul2(m[k], st), NLRT2, cl[k]);
            }
        }
        #pragma unroll
        for (int k = 0; k < 3; k++) {
            float lo, hi; upk(cl[k], lo, hi);
            chOutA[k] = lo * LN2_F;
            chOutB[k] = hi * LN2_F;
        }
    } else {
        // ===== general two-pass fallback (dense Se, Sa) — packed 2px, ch domain =====
        F2 ch[3];
        #pragma unroll
        for (int k = 0; k < 3; k++)
            ch[k] = pk(ch0g[pA*3 + k], ch0g[pB*3 + k]);

        const F2 CNA = bc(cna), CNBp = bc(cnb);
        const F2 C7p = bc(c7s), C8p = bc(c8s), C82 = bc(2.0f*c8s);
        const F2 C0045 = bc(0.0045f), C0012 = bc(0.0012f);
        const F2 NEG1 = bc(-1.0f), ONEg = bc(1.0f);
        const F2 CB1p = bc(ADAM_B1), C1MB1p = bc(1.0f - ADAM_B1);
        const F2 CB2p = bc(ADAM_B2), C1MB2p = bc(1.0f - ADAM_B2);
        const F2 APH[5] = { bc(AphS[0]), bc(AphS[1]), bc(AphS[2]), bc(AphS[3]), bc(AphS[4]) };
        const F2 ACD[5] = { bc(AcdS[0]), bc(AcdS[1]), bc(AcdS[2]), bc(AcdS[3]), bc(AcdS[4]) };
        const F2 BBS[5] = { bc(BbsS[0]), bc(BbsS[1]), bc(BbsS[2]), bc(BbsS[3]), bc(BbsS[4]) };
        F2 FE[5], Yp[5];
        #pragma unroll
        for (int l = 0; l < 5; l++) {
            FE[l] = pk(feA[l], feB[l]);
            Yp[l] = pk(-Yg[pA*5 + l], -Yg[pB*5 + l]);
        }
        float bp0 = -(SaS[0][0]*xa0 + SaS[0][1]*xa1 + SaS[0][2]*xa2);
        float bp1 = -(SaS[1][0]*xa0 + SaS[1][1]*xa1 + SaS[1][2]*xa2);
        float bp2 = -(SaS[2][0]*xa0 + SaS[2][1]*xa1 + SaS[2][2]*xa2);

        for (int t = 0; t < iters; t++) {
            F2 chla = fexp2(ch[0]);
            F2 nap  = fexp2(ch[1]);
            F2 cdom = fexp2(ch[2]);

            F2 da1  = fmul2(CNA, nap);
            F2 dbb1 = fmul2(CNBp, nap);

            F2 u[5], iv[5];
            float rA[5], rB[5];
            #pragma unroll
            for (int l = 0; l < 5; l++) {
                F2 da0  = fmul2(APH[l], chla);
                F2 da2  = fmul2(ACD[l], cdom);
                F2 dbb0 = fmul2(BBS[l], chla);
                F2 a  = fadd2(fadd2(da0, da2), fadd2(da1, C0045));
                F2 bb = fadd2(dbb0, fadd2(dbb1, C0012));
                F2 ivv = frcp2(fadd2(a, bb));
                F2 uv  = fmul2(bb, ivv);
                F2 rrs = fmul2(fmul2(ffma2(C8p, uv, C7p), uv), FE[l]);
                F2 rr  = fadd2(rrs, Yp[l]);
                upk(rr, rA[l], rB[l]);
                u[l] = uv; iv[l] = ivv;
            }

            float cA0, cB0, cA1, cB1, cA2, cB2;
            upk(ch[0], cA0, cB0); upk(ch[1], cA1, cB1); upk(ch[2], cA2, cB2);
            float gA0 = fmaf(SaS[0][0], cA0, fmaf(SaS[0][1], cA1, fmaf(SaS[0][2], cA2, bp0)));
            float gB0 = fmaf(SaS[0][0], cB0, fmaf(SaS[0][1], cB1, fmaf(SaS[0][2], cB2, bp0)));
            float gA1 = fmaf(SaS[1][0], cA0, fmaf(SaS[1][1], cA1, fmaf(SaS[1][2], cA2, bp1)));
            float gB1 = fmaf(SaS[1][0], cB0, fmaf(SaS[1][1], cB1, fmaf(SaS[1][2], cB2, bp1)));
            float gA2 = fmaf(SaS[2][0], cA0, fmaf(SaS[2][1], cA1, fmaf(SaS[2][2], cA2, bp2)));
            float gB2 = fmaf(SaS[2][0], cB0, fmaf(SaS[2][1], cB1, fmaf(SaS[2][2], cB2, bp2)));
            F2 g0 = pk(gA0, gB0);
            F2 g1 = pk(gA1, gB1);
            F2 g2 = pk(gA2, gB2);

            #pragma unroll
            for (int l = 0; l < 5; l++) {
                float wA = fmaf(Se[l][4], rA[4],
                           fmaf(Se[l][0], rA[0], Se[l][1]*rA[1]) +
                           fmaf(Se[l][2], rA[2], Se[l][3]*rA[3]));
                float wB = fmaf(Se[l][4], rB[4],
                           fmaf(Se[l][0], rB[0], Se[l][1]*rB[1]) +
                           fmaf(Se[l][2], rB[2], Se[l][3]*rB[3]));
                F2 w  = pk(wA, wB);
                F2 dg = fmul2(ffma2(C82, u[l], C7p), FE[l]);
                F2 q  = fmul2(fmul2(w, dg), iv[l]);

                F2 da0  = fmul2(APH[l], chla);
                F2 dbb0 = fmul2(BBS[l], chla);
                F2 da2  = fmul2(ACD[l], cdom);
                F2 om   = ffma2(u[l], NEG1, ONEg);

                F2 x0 = ffma2(fmul2(u[l], da0), NEG1, fmul2(om, dbb0));
                F2 x1 = ffma2(fmul2(u[l], da1), NEG1, fmul2(om, dbb1));
                F2 qun = fmul2(fmul2(q, u[l]), NEG1);
                g0 = ffma2(q, x0, g0);
                g1 = ffma2(q, x1, g1);
                g2 = ffma2(qun, da2, g2);
            }

            b1t *= ADAM_B1; b2t *= ADAM_B2;
            float nlrt = -ADAM_LR * sqrt_a(1.0f - b2t) * rcp_a(1.0f - b1t);
            F2 NLRT2 = bc(nlrt);
            F2 g[3] = { g0, g1, g2 };
            #pragma unroll
            for (int k = 0; k < 3; k++) {
                m[k] = ffma2(g[k], C1MB1p, fmul2(m[k], CB1p));
                v[k] = ffma2(fmul2(g[k], g[k]), C1MB2p, fmul2(v[k], CB2p));
                F2 st = frsq2(v[k]);
                ch[k] = ffma2(fmul2(m[k], st), NLRT2, ch[k]);
            }
        }
        #pragma unroll
        for (int k = 0; k < 3; k++) {
            float lo, hi; upk(ch[k], lo, hi);
            chOutA[k] = lo;
            chOutB[k] = hi;
        }
    }

    // ---- outputs: [ch0, kd(5), bbp(3)] per pixel ----
    float kfac = p9 * 0.9f + p10 * 0.1f;

    #pragma unroll
    for (int s = 0; s < 2; s++) {
        int b = s ? pB : pA;
        const float* chp = s ? chOutB : chOutA;
        float chla = EXPA(chp[0]);
        float nap  = EXPA(chp[1]);
        float cdom = EXPA(chp[2]);

        out[b*9 + 0] = chp[0];
        #pragma unroll
        for (int l = 0; l < 5; l++) {
            float a  = 0.0045f + AphS[l]*chla + AcdS[l]*cdom + cna*nap;
            float bb = 0.0012f + BbsS[l]*chla + cnb*nap;
            float x3 = X[b*25 + l*5 + 3];
            float mu = 0.5f + 0.5f * rcp_a(1.0f + EXPA(-x3));
            out[b*9 + 1 + l] = (a + bb) * rcp_a(mu) * kfac;
        }
        const float L3[3] = {0.025f, 0.5f, 1.15f};
        #pragma unroll
        for (int j = 0; j < 3; j++) {
            out[b*9 + 6 + j] = p11 * (p3 * 0.001f * chla * (1.0f + p4 * 0.05f * L3[j]) + cnb * nap);
        }
    }
}

extern "C" void kernel_launch(void* const* d_in, const int* in_sizes, int n_in,
                              void* d_out, int out_size) {
    const float* X    = (const float*)d_in[0];
    const float* Y    = (const float*)d_in[1];
    const float* ch0  = (const float*)d_in[2];
    const float* pf   = (const float*)d_in[3];
    const float* xa   = (const float*)d_in[4];
    const float* Sa   = (const float*)d_in[5];
    const float* Se   = (const float*)d_in[6];
    const int*   nit  = (n_in >= 8) ? (const int*)d_in[7] : nullptr;
    float* out = (float*)d_out;

    int B = in_sizes[1] / 5;   // Y is (B,5)
    int nThreads = (B + 1) / 2;

    const int TPB = 32;
    int blocks = (nThreads + TPB - 1) / TPB;
    pe_kernel<<<blocks, TPB>>>(X, Y, ch0, pf, xa, Sa, Se, nit, out, B);
}